// round 8
// baseline (speedup 1.0000x reference)
#include <cuda_runtime.h>
#include <cuda_fp16.h>
#include <cstdint>

#define N_TOK 16384
#define DIN   768
#define NEXP  8
#define HDIM  2048

#define BM 128
#define BN 256
#define BK 16
#define PH 24   // smem row pitch in halfs (48B = 3*16B): full-warp conflict-free

// ---------------- device scratch ----------------
__device__ __align__(256) int    g_count[NEXP];
__device__ __align__(256) int    g_list[NEXP * N_TOK];
__device__ __align__(256) int    g_expert[N_TOK];
__device__ __align__(256) float  g_prob[N_TOK];
__device__ __align__(256) __half g_latent[(size_t)N_TOK * HDIM];   // fp16 latent

// ---------------- mma helper ----------------
__device__ __forceinline__ void mma_f16(float& c0, float& c1, float& c2, float& c3,
                                        uint32_t a0, uint32_t a1, uint32_t a2, uint32_t a3,
                                        uint32_t b0, uint32_t b1) {
    asm volatile("mma.sync.aligned.m16n8k16.row.col.f32.f16.f16.f32 "
                 "{%0,%1,%2,%3}, {%4,%5,%6,%7}, {%8,%9}, {%0,%1,%2,%3};\n"
                 : "+f"(c0), "+f"(c1), "+f"(c2), "+f"(c3)
                 : "r"(a0), "r"(a1), "r"(a2), "r"(a3), "r"(b0), "r"(b1));
}

// ---------------- small kernels ----------------
__global__ void zero_counts_kernel() {
    if (threadIdx.x < NEXP) g_count[threadIdx.x] = 0;
}

__global__ void router_kernel(const float* __restrict__ x,
                              const float* __restrict__ router_b,
                              const float* __restrict__ router) {
    const int warp = threadIdx.x >> 5, lane = threadIdx.x & 31;
    const int tok = blockIdx.x * 8 + warp;
    float acc[8];
#pragma unroll
    for (int e = 0; e < 8; e++) acc[e] = 0.f;
    const float* xr = x + (size_t)tok * DIN;
    for (int d = lane; d < DIN; d += 32) {
        float xv = xr[d] - router_b[d];
        float4 ra = *(const float4*)(router + d * 8);
        float4 rb = *(const float4*)(router + d * 8 + 4);
        acc[0] += xv * ra.x; acc[1] += xv * ra.y;
        acc[2] += xv * ra.z; acc[3] += xv * ra.w;
        acc[4] += xv * rb.x; acc[5] += xv * rb.y;
        acc[6] += xv * rb.z; acc[7] += xv * rb.w;
    }
#pragma unroll
    for (int e = 0; e < 8; e++) {
#pragma unroll
        for (int off = 16; off > 0; off >>= 1)
            acc[e] += __shfl_xor_sync(0xffffffffu, acc[e], off);
    }
    if (lane == 0) {
        float m = acc[0]; int idx = 0;
#pragma unroll
        for (int e = 1; e < 8; e++) if (acc[e] > m) { m = acc[e]; idx = e; }
        float s = 0.f;
#pragma unroll
        for (int e = 0; e < 8; e++) s += expf(acc[e] - m);
        g_expert[tok] = idx;
        g_prob[tok] = 1.f / s;
    }
}

__global__ void build_lists_kernel() {
    const int t = blockIdx.x * blockDim.x + threadIdx.x;
    if (t >= N_TOK) return;
    const int e = g_expert[t];
    const int pos = atomicAdd(&g_count[e], 1);
    g_list[e * N_TOK + pos] = t;
}

// ---------------- fp16 tensor-core gather-GEMM: 128x256 tile, 64x64 warp tiles ----------------
// A: gathered token rows (fp32 x -> cvt, or fp16 latent direct). B: W[k][n] strided fp32 -> cvt,
// staged transposed [n][k]. Static smem: A 2*6144B + B 2*12288B = 36864B.
template<int KTOT, bool G1>
__global__ void __launch_bounds__(256) sae_gemm_kernel(
    const float* __restrict__ x, const float* __restrict__ W,
    const float* __restrict__ pre_b, float* __restrict__ out)
{
    const int e = blockIdx.z;
    const int cnt = g_count[e];
    const int mBase = blockIdx.y * BM;
    if (mBase >= cnt) return;
    const int nBase = blockIdx.x * BN;
    const int ldB = G1 ? HDIM : DIN;
    const float* We = W + (size_t)e * KTOT * ldB;
    const int* list = g_list + e * N_TOK;

    __shared__ __half As[2][BM * PH];
    __shared__ __half Bs[2][BN * PH];

    const int tid = threadIdx.x, lane = tid & 31, warp = tid >> 5;
    const int wm = (warp >> 2) * 64, wn = (warp & 3) * 64;
    const int grp = lane >> 2, tig = lane & 3;

    // A staging: threads 0..127 own one token row each (16 halfs/chunk)
    const int tokS = (tid < BM && mBase + tid < cnt) ? list[mBase + tid] : -1;
    // B staging: all 256 threads own one n column (16 k values/chunk, strided)
    const float* bCol = We + nBase + tid;

    float4 a4[4];
    uint4  al[2];
    float  bf[16];

    auto fetch = [&](int c) {
        if (tid < BM) {
            if (G1) {
                if (tokS >= 0) {
                    const float4* p = (const float4*)(x + (size_t)tokS * KTOT + c * BK);
                    a4[0] = __ldg(p); a4[1] = __ldg(p + 1);
                    a4[2] = __ldg(p + 2); a4[3] = __ldg(p + 3);
                } else {
                    a4[0] = a4[1] = a4[2] = a4[3] = make_float4(0.f, 0.f, 0.f, 0.f);
                }
            } else {
                if (tokS >= 0) {
                    const uint4* p = (const uint4*)(g_latent + (size_t)tokS * KTOT + c * BK);
                    al[0] = __ldg(p); al[1] = __ldg(p + 1);
                } else {
                    al[0] = al[1] = make_uint4(0u, 0u, 0u, 0u);
                }
            }
        }
        const float* bp = bCol + (size_t)(c * BK) * ldB;
#pragma unroll
        for (int j = 0; j < 16; j++) bf[j] = __ldg(bp + (size_t)j * ldB);
    };

    auto stage = [&](int buf) {
        if (tid < BM) {
            uint4* a = (uint4*)&As[buf][tid * PH];
            if (G1) {
                __half2 h[8];
                h[0] = __floats2half2_rn(a4[0].x, a4[0].y); h[1] = __floats2half2_rn(a4[0].z, a4[0].w);
                h[2] = __floats2half2_rn(a4[1].x, a4[1].y); h[3] = __floats2half2_rn(a4[1].z, a4[1].w);
                h[4] = __floats2half2_rn(a4[2].x, a4[2].y); h[5] = __floats2half2_rn(a4[2].z, a4[2].w);
                h[6] = __floats2half2_rn(a4[3].x, a4[3].y); h[7] = __floats2half2_rn(a4[3].z, a4[3].w);
                const uint4* q = (const uint4*)h;
                a[0] = q[0]; a[1] = q[1];
            } else {
                a[0] = al[0]; a[1] = al[1];
            }
        }
        uint4* b = (uint4*)&Bs[buf][tid * PH];
        __half2 hb[8];
#pragma unroll
        for (int j = 0; j < 8; j++) hb[j] = __floats2half2_rn(bf[2 * j], bf[2 * j + 1]);
        const uint4* qb = (const uint4*)hb;
        b[0] = qb[0]; b[1] = qb[1];
    };

    float c[4][8][4];
#pragma unroll
    for (int mi = 0; mi < 4; mi++)
#pragma unroll
        for (int ni = 0; ni < 8; ni++)
#pragma unroll
            for (int j = 0; j < 4; j++) c[mi][ni][j] = 0.f;

    fetch(0); stage(0);
    __syncthreads();

    const int KT = KTOT / BK;      // G1: 48, G2: 128
    for (int kt = 0; kt < KT; ++kt) {
        const int buf = kt & 1;
        if (kt + 1 < KT) fetch(kt + 1);

        uint32_t aF[4][4], bF[8][2];
#pragma unroll
        for (int mi = 0; mi < 4; mi++) {
            const __half* ab = &As[buf][(wm + mi * 16 + grp) * PH + 2 * tig];
            aF[mi][0] = *(const uint32_t*)ab;
            aF[mi][1] = *(const uint32_t*)(ab + 8 * PH);
            aF[mi][2] = *(const uint32_t*)(ab + 8);
            aF[mi][3] = *(const uint32_t*)(ab + 8 * PH + 8);
        }
#pragma unroll
        for (int ni = 0; ni < 8; ni++) {
            const __half* bb = &Bs[buf][(wn + ni * 8 + grp) * PH + 2 * tig];
            bF[ni][0] = *(const uint32_t*)bb;
            bF[ni][1] = *(const uint32_t*)(bb + 8);
        }
#pragma unroll
        for (int mi = 0; mi < 4; mi++)
#pragma unroll
            for (int ni = 0; ni < 8; ni++)
                mma_f16(c[mi][ni][0], c[mi][ni][1], c[mi][ni][2], c[mi][ni][3],
                        aF[mi][0], aF[mi][1], aF[mi][2], aF[mi][3],
                        bF[ni][0], bF[ni][1]);

        if (kt + 1 < KT) stage(buf ^ 1);
        __syncthreads();
    }

    // ---- epilogue ----
#pragma unroll
    for (int mi = 0; mi < 4; mi++) {
        const int r0 = mBase + wm + mi * 16 + grp;
        const int r1 = r0 + 8;
        const int t0 = (r0 < cnt) ? list[r0] : -1;
        const int t1 = (r1 < cnt) ? list[r1] : -1;
        float p0 = 0.f, p1 = 0.f;
        if (!G1) {
            p0 = (t0 >= 0) ? g_prob[t0] : 0.f;
            p1 = (t1 >= 0) ? g_prob[t1] : 0.f;
        }
#pragma unroll
        for (int ni = 0; ni < 8; ni++) {
            const int col = nBase + wn + ni * 8 + tig * 2;
            if (G1) {
                if (t0 >= 0) {
                    __half2 v = __floats2half2_rn(fmaxf(c[mi][ni][0], 0.f), fmaxf(c[mi][ni][1], 0.f));
                    *(__half2*)(g_latent + (size_t)t0 * HDIM + col) = v;
                }
                if (t1 >= 0) {
                    __half2 v = __floats2half2_rn(fmaxf(c[mi][ni][2], 0.f), fmaxf(c[mi][ni][3], 0.f));
                    *(__half2*)(g_latent + (size_t)t1 * HDIM + col) = v;
                }
            } else {
                const float pb0 = __ldg(pre_b + col), pb1 = __ldg(pre_b + col + 1);
                if (t0 >= 0) {
                    float2 v = make_float2(p0 * c[mi][ni][0] + pb0, p0 * c[mi][ni][1] + pb1);
                    *(float2*)(out + (size_t)t0 * DIN + col) = v;
                }
                if (t1 >= 0) {
                    float2 v = make_float2(p1 * c[mi][ni][2] + pb0, p1 * c[mi][ni][3] + pb1);
                    *(float2*)(out + (size_t)t1 * DIN + col) = v;
                }
            }
        }
    }
}

// ---------------- launcher ----------------
extern "C" void kernel_launch(void* const* d_in, const int* in_sizes, int n_in,
                              void* d_out, int out_size) {
    const float* x        = (const float*)d_in[0];
    const float* pre_b    = (const float*)d_in[1];
    const float* enc      = (const float*)d_in[2];
    const float* dec      = (const float*)d_in[3];
    const float* router_b = (const float*)d_in[4];
    const float* router   = (const float*)d_in[5];
    float* out = (float*)d_out;

    zero_counts_kernel<<<1, 32>>>();
    router_kernel<<<N_TOK / 8, 256>>>(x, router_b, router);
    build_lists_kernel<<<N_TOK / 256, 256>>>();

    dim3 g1(HDIM / BN, N_TOK / BM, NEXP);   // (8, 128, 8) — most tiles early-exit
    sae_gemm_kernel<DIN, true><<<g1, 256>>>(x, enc, pre_b, out);

    dim3 g2(DIN / BN, N_TOK / BM, NEXP);    // (3, 128, 8)
    sae_gemm_kernel<HDIM, false><<<g2, 256>>>(x, dec, pre_b, out);
}